// round 15
// baseline (speedup 1.0000x reference)
#include <cuda_runtime.h>
#include <cuda_bf16.h>

#define MAX_M 600000          // corners
#define EPSF 1e-8f
#define WSCALE 0.99f

// Scratch (no cudaMalloc allowed). Zero-init at load = valid empty state;
// k_world resets every touched slot to 0 so graph replays stay deterministic.
__device__ int    g_winner[MAX_M];   // (last flat writer index)+1 ; 0 = empty
__device__ float4 g_ws[MAX_M];       // (world.x, world.y, world.z, sdf)

// --- HW approx ops: 1 MUFU each ---
__device__ __forceinline__ float fast_rcp(float x)   { float r; asm("rcp.approx.f32 %0,%1;"   : "=f"(r) : "f"(x)); return r; }
__device__ __forceinline__ float fast_rsqrt(float x) { float r; asm("rsqrt.approx.f32 %0,%1;" : "=f"(r) : "f"(x)); return r; }
__device__ __forceinline__ float fast_sqrt(float x)  { float r; asm("sqrt.approx.f32 %0,%1;"  : "=f"(r) : "f"(x)); return r; }
__device__ __forceinline__ float fast_tanh(float x)  { float r; asm("tanh.approx.f32 %0,%1;"  : "=f"(r) : "f"(x)); return r; }

// ---------------------------------------------------------------------------
// Kernel 1: winner = max flat index writing each slot (== JAX last-write-wins
// scatter). 32-bit atomics; stores k+1 so zero means "empty".
// ---------------------------------------------------------------------------
__global__ void k_scatter(const int4* __restrict__ cube_idx, int total4, int M) {
    int t = blockIdx.x * blockDim.x + threadIdx.x;
    if (t >= total4) return;
    int4 v = cube_idx[t];
    int k = t * 4;
    int j;
    j = v.x; if (j < 0) j = 0; if (j >= M) j = M - 1; atomicMax(&g_winner[j], k + 1);
    j = v.y; if (j < 0) j = 0; if (j >= M) j = M - 1; atomicMax(&g_winner[j], k + 2);
    j = v.z; if (j < 0) j = 0; if (j >= M) j = M - 1; atomicMax(&g_winner[j], k + 3);
    j = v.w; if (j < 0) j = 0; if (j >= M) j = M - 1; atomicMax(&g_winner[j], k + 4);
}

// ---------------------------------------------------------------------------
// Kernel 2: 4 corners per thread, fully vectorized streams.
// g_ws[j] = (world.xyz, sdf[j]); resets g_winner[j] = 0.
// world = (vox[winner/8] + corner(winner&7)) * (2/res) - 1 + deform.
// M = 600000 is divisible by 4.
// ---------------------------------------------------------------------------
__global__ void k_world(const int* __restrict__ vox,
                        const float* __restrict__ deform,
                        const float* __restrict__ sdf,
                        int M4, float scale) {
    int t = blockIdx.x * blockDim.x + threadIdx.x;
    if (t >= M4) return;
    int j0 = t * 4;

    int4 w4 = *(const int4*)(g_winner + j0);
    *(int4*)(g_winner + j0) = make_int4(0, 0, 0, 0);   // reset for next replay

    const float4* dp = (const float4*)(deform + (size_t)j0 * 3);
    float4 d0 = dp[0], d1 = dp[1], d2 = dp[2];         // 12 floats = 4 corners xyz
    float4 s4 = *(const float4*)(sdf + j0);

    float dx[4] = {d0.x, d0.w, d1.z, d2.y};
    float dy[4] = {d0.y, d1.x, d1.w, d2.z};
    float dz[4] = {d0.z, d1.y, d2.x, d2.w};
    float sv[4] = {s4.x, s4.y, s4.z, s4.w};
    int   wn[4] = {w4.x, w4.y, w4.z, w4.w};

#pragma unroll
    for (int q = 0; q < 4; q++) {
        int w = wn[q];
        float px = 0.f, py = 0.f, pz = 0.f;
        if (w > 0) {
            int k = w - 1;
            int i = k >> 3, c = k & 7;
            px = (float)vox[i * 3 + 0] + (float)(c & 1);
            py = (float)vox[i * 3 + 1] + (float)((c >> 1) & 1);
            pz = (float)vox[i * 3 + 2] + (float)((c >> 2) & 1);
        }
        float4 ws;
        ws.x = px * scale - 1.f + dx[q];
        ws.y = py * scale - 1.f + dy[q];
        ws.z = pz * scale - 1.f + dz[q];
        ws.w = sv[q];
        g_ws[j0 + q] = ws;
    }
}

// ---------------------------------------------------------------------------
// Kernel 3: per-cube dual-contouring math (HW approx ops, invd cached across
// passes). One thread per cube, 256/block.
// Outputs (flat concat): [vertices 3N][L_dev 12N][p_alpha 3N][n_out 3N]
// ---------------------------------------------------------------------------
__global__ void __launch_bounds__(256)
k_main(const int* __restrict__ cube_idx,
       const float* __restrict__ alpha,
       const float* __restrict__ beta,
       float* __restrict__ out, int N) {
    int i = blockIdx.x * blockDim.x + threadIdx.x;
    if (i >= N) return;

    // --- corner indices (coalesced int4 loads) ---
    const int4* cp = (const int4*)(cube_idx + (size_t)i * 8);
    int4 ca = cp[0], cb = cp[1];
    int ci[8] = {ca.x, ca.y, ca.z, ca.w, cb.x, cb.y, cb.z, cb.w};

    // --- one LDG.128 gather per corner: world.xyz + sdf ---
    float s[8], wx[8], wy[8], wz[8];
    bool anyp = false, anyn = false;
#pragma unroll
    for (int c = 0; c < 8; c++) {
        float4 w = __ldg(&g_ws[ci[c]]);
        wx[c] = w.x; wy[c] = w.y; wz[c] = w.z;
        s[c] = w.w;
        anyp |= (w.w > 0.f);
        anyn |= !(w.w > 0.f);
    }
    bool surf = anyp && anyn;

    // --- alpha weights (HW tanh) ---
    const float4* ap = (const float4*)(alpha + (size_t)i * 8);
    float4 av0 = ap[0], av1 = ap[1];
    float aarr[8] = {av0.x, av0.y, av0.z, av0.w, av1.x, av1.y, av1.z, av1.w};
    float an[8];
#pragma unroll
    for (int c = 0; c < 8; c++) an[c] = fast_tanh(aarr[c]) * WSCALE + 1.f;

    const float4* bp = (const float4*)(beta + (size_t)i * 12);
    float4 bv0 = bp[0], bv1 = bp[1], bv2 = bp[2];
    float barr[12] = {bv0.x, bv0.y, bv0.z, bv0.w, bv1.x, bv1.y, bv1.z, bv1.w,
                      bv2.x, bv2.y, bv2.z, bv2.w};

    const int E0[12] = {0, 1, 4, 0, 2, 3, 6, 2, 2, 3, 7, 6};
    const int E1[12] = {1, 5, 5, 4, 3, 7, 7, 6, 0, 1, 5, 4};

    // --- pass 1: wsum, vd and n_alpha accumulation; invd cached ---
    unsigned cmask = 0;
    float invdv[12];
    float wsum = 0.f;
    float vdx = 0.f, vdy = 0.f, vdz = 0.f;
    float nax = 0.f, nay = 0.f, naz = 0.f;
#pragma unroll
    for (int e = 0; e < 12; e++) {
        int c0 = E0[e], c1 = E1[e];
        float s0 = s[c0], s1 = s[c1];
        bool cr = ((s0 > 0.f) != (s1 > 0.f)) && surf;
        cmask |= (cr ? 1u : 0u) << e;
        float wb = cr ? (fast_tanh(barr[e]) * WSCALE + 1.f) : 0.f;
        wsum += wb;

        float w0 = an[c0] * fabsf(s0);
        float w1 = an[c1] * fabsf(s1);
        float invd = fast_rcp(w0 + w1 + EPSF);
        invdv[e] = invd;
        float t = wb * invd;
        vdx += (wx[c0] * w1 + wx[c1] * w0) * t;
        vdy += (wy[c0] * w1 + wy[c1] * w0) * t;
        vdz += (wz[c0] * w1 + wz[c1] * w0) * t;

        float evx = wx[c1] - wx[c0];
        float evy = wy[c1] - wy[c0];
        float evz = wz[c1] - wz[c0];
        float dot = evx * evx + evy * evy + evz * evz;
        float f = copysignf(fast_rsqrt(dot + 1e-30f), s1 - s0) * wb;
        nax += evx * f; nay += evy * f; naz += evz * f;
    }

    float invw = fast_rcp(wsum + EPSF);
    vdx *= invw; vdy *= invw; vdz *= invw;
    nax *= invw; nay *= invw; naz *= invw;
    float innn = fast_rsqrt(nax * nax + nay * nay + naz * naz + 1e-30f);
    nax *= innn; nay *= innn; naz *= innn;

    // --- pass 2: recompute ue (invd cached), distances to vd ---
    float dist[12];
    float sumd = 0.f, ne = 0.f;
#pragma unroll
    for (int e = 0; e < 12; e++) {
        int c0 = E0[e], c1 = E1[e];
        float cmf = (cmask >> e) & 1u ? 1.f : 0.f;
        float w0 = an[c0] * fabsf(s[c0]);
        float w1 = an[c1] * fabsf(s[c1]);
        float invd = invdv[e];
        float dx = (wx[c0] * w1 + wx[c1] * w0) * invd - vdx;
        float dy = (wy[c0] * w1 + wy[c1] * w0) * invd - vdy;
        float dz = (wz[c0] * w1 + wz[c1] * w0) * invd - vdz;
        float d = fast_sqrt(dx * dx + dy * dy + dz * dz) * cmf;
        dist[e] = d;
        sumd += d;
        ne += cmf;
    }
    float mean = sumd * fast_rcp(ne + EPSF);

    // --- outputs ---
    float sm = surf ? 1.f : 0.f;
    size_t Ns = (size_t)N;
    float* vout = out;                 // vertices: 3N
    float* ldev = out + 3 * Ns;        // L_dev:   12N
    float* pout = out + 15 * Ns;       // p_alpha:  3N
    float* nout = out + 18 * Ns;       // n_out:    3N

    float vx = vdx * sm, vy = vdy * sm, vz = vdz * sm;
    vout[i * 3 + 0] = vx; vout[i * 3 + 1] = vy; vout[i * 3 + 2] = vz;
    pout[i * 3 + 0] = vx; pout[i * 3 + 1] = vy; pout[i * 3 + 2] = vz;
    nout[i * 3 + 0] = nax * sm; nout[i * 3 + 1] = nay * sm; nout[i * 3 + 2] = naz * sm;

    float ld[12];
#pragma unroll
    for (int e = 0; e < 12; e++) {
        float cmf = (cmask >> e) & 1u ? 1.f : 0.f;
        ld[e] = fabsf(dist[e] - mean) * cmf;
    }
    float4* lp = (float4*)(ldev + (size_t)i * 12);
    lp[0] = make_float4(ld[0], ld[1], ld[2], ld[3]);
    lp[1] = make_float4(ld[4], ld[5], ld[6], ld[7]);
    lp[2] = make_float4(ld[8], ld[9], ld[10], ld[11]);
}

// ---------------------------------------------------------------------------
extern "C" void kernel_launch(void* const* d_in, const int* in_sizes, int n_in,
                              void* d_out, int out_size) {
    int N = in_sizes[0] / 3;
    int M = in_sizes[1];
    int base = (n_in >= 8 && in_sizes[3] == 1) ? 4 : 3;

    const int*   vox    = (const int*)d_in[0];
    const float* sdf    = (const float*)d_in[1];
    const int*   cidx   = (const int*)d_in[2];
    const float* deform = (const float*)d_in[base + 0];
    const float* beta   = (const float*)d_in[base + 1];
    const float* alpha  = (const float*)d_in[base + 2];
    float* out = (float*)d_out;

    int total4 = N * 2;                  // N*8 indices / 4 per thread
    int M4 = M / 4;                      // M divisible by 4 (600000)
    const float scale = 2.0f / 256.0f;

    k_scatter<<<(total4 + 255) / 256, 256>>>((const int4*)cidx, total4, M);
    k_world  <<<(M4 + 255) / 256, 256>>>(vox, deform, sdf, M4, scale);
    k_main   <<<(N + 255) / 256, 256>>>(cidx, alpha, beta, out, N);
}